// round 13
// baseline (speedup 1.0000x reference)
#include <cuda_runtime.h>
#include <cstddef>

// Involution (B=8, H=W=192, C=64, G=4, K=3, R=4 -> cr=16)
// R13: R12 (32x16 tile, 4 vertical px/thread, channel-split smem, const
// weights, cp.async) + t[2..3] stashed to smem to cap register peak ~186
// and eliminate spills.

#define HH 192
#define WW 192
#define CC 64
#define CR 16
#define TAPS 9

constexpr int TW = 16;                                // tile width
constexpr int TH = 32;                                // tile height
constexpr int HW = 18;                                // halo width
constexpr int HT = 34;                                // halo height
constexpr int PSTR = 9;                               // f4 per pixel (8 data + 1 pad)
constexpr int TILE_F4 = HT * HW * PSTR;               // 5508
constexpr int TBUF_FLOATS = 2 * CR * 128;             // t[2],t[3] transposed
constexpr int SMEM_BYTES = TILE_F4 * 16 + TBUF_FLOATS * 4;  // 104512 B

struct ConstW {
    float4 w1[256];   // [c4=16][d=16], BN folded
    float4 w2[144];   // [d=16][tap=9], f4 over 4 groups
    float4 b2[9];
    float  b1[16];    // BN-folded bias
};
__constant__ ConstW cW;
__device__ ConstW scratchW;

__global__ void involution_prep_kernel(const float* __restrict__ w1,
                                       const float* __restrict__ b1,
                                       const float* __restrict__ gamma,
                                       const float* __restrict__ beta,
                                       const float* __restrict__ mean,
                                       const float* __restrict__ var,
                                       const float* __restrict__ w2,
                                       const float* __restrict__ b2) {
    __shared__ float s[16];
    int tid = threadIdx.x;   // 256 threads
    if (tid < 16) {
        float sc = gamma[tid] * rsqrtf(var[tid] + 1e-3f);
        s[tid] = sc;
        scratchW.b1[tid] = (b1[tid] - mean[tid]) * sc + beta[tid];
    }
    __syncthreads();
    {
        int d  = tid & 15;
        int c4 = tid >> 4;
        float sc = s[d];
        scratchW.w1[tid] = make_float4(w1[(4 * c4 + 0) * CR + d] * sc,
                                       w1[(4 * c4 + 1) * CR + d] * sc,
                                       w1[(4 * c4 + 2) * CR + d] * sc,
                                       w1[(4 * c4 + 3) * CR + d] * sc);
    }
    if (tid < 144) scratchW.w2[tid] = ((const float4*)w2)[tid];
    if (tid < 9)   scratchW.b2[tid] = ((const float4*)b2)[tid];
}

__device__ __forceinline__ void fma4(float4& a, const float4& k, const float4& v) {
    a.x = fmaf(k.x, v.x, a.x);
    a.y = fmaf(k.y, v.y, a.y);
    a.z = fmaf(k.z, v.z, a.z);
    a.w = fmaf(k.w, v.w, a.w);
}

__device__ __forceinline__ void cp16(unsigned dst, const void* src, int sz) {
    asm volatile("cp.async.cg.shared.global [%0], [%1], 16, %2;"
                 :: "r"(dst), "l"(src), "r"(sz) : "memory");
}

// load one channel-half (u base = uoff) of the 34x18 halo tile, zero-fill OOB
__device__ __forceinline__ void load_tile_half(unsigned smem_base,
                                               const float* __restrict__ xb,
                                               int gy0, int gx0, int uoff, int tid) {
    for (int s = tid; s < HT * HW * 8; s += 128) {
        int u   = s & 7;
        int pix = s >> 3;
        int py  = pix / HW;
        int px  = pix - py * HW;
        int gh  = gy0 - 1 + py;
        int gw  = gx0 - 1 + px;
        bool ok = ((unsigned)gh < HH) && ((unsigned)gw < WW);
        const float4* src = (const float4*)(xb + ((size_t)(ok ? gh : 0) * WW + (ok ? gw : 0)) * CC)
                            + uoff + u;
        cp16(smem_base + (unsigned)(pix * PSTR + u) * 16u, src, ok ? 16 : 0);
    }
    asm volatile("cp.async.commit_group;\n\tcp.async.wait_group 0;" ::: "memory");
}

__global__ __launch_bounds__(128, 2)
void involution_fused_kernel(const float* __restrict__ x,
                             float* __restrict__ out) {
    extern __shared__ float4 tile4[];              // [34*18 px][9 f4]
    float* tbuf = (float*)(tile4 + TILE_F4);       // [p(2)][d(16)][tid(128)]

    const int tid = threadIdx.x;              // 0..127
    const int tx  = tid & 15;
    const int qy  = tid >> 4;                 // 0..7 -> output rows 4qy..4qy+3
    const int gx0 = blockIdx.x * TW;
    const int gy0 = blockIdx.y * TH;
    const int bz  = blockIdx.z;

    const float* xb = x + (size_t)bz * ((size_t)HH * WW * CC);
    unsigned smem_base = (unsigned)__cvta_generic_to_shared(tile4);

    // ---- tile half u0-7 ----
    load_tile_half(smem_base, xb, gy0, gx0, 0, tid);
    __syncthreads();

    // ---- phase B: t[p][d] = relu(x_p . w1' + b1'), 4 vertical pixels ----
    const float4* xc[4];
    const float4* gp[4];
    #pragma unroll
    for (int p = 0; p < 4; p++) {
        xc[p] = tile4 + ((4 * qy + p + 1) * HW + (tx + 1)) * PSTR;
        gp[p] = (const float4*)(xb + ((size_t)(gy0 + 4 * qy + p) * WW + gx0 + tx) * CC);
    }

    float t[4][CR];
    #pragma unroll
    for (int d = 0; d < CR; d++) {
        float b = cW.b1[d];
        t[0][d] = b; t[1][d] = b; t[2][d] = b; t[3][d] = b;
    }

    #pragma unroll 2
    for (int c4 = 0; c4 < 8; c4++) {               // first channel half from smem
        float4 xv0 = xc[0][c4], xv1 = xc[1][c4], xv2 = xc[2][c4], xv3 = xc[3][c4];
        #pragma unroll
        for (int d = 0; d < CR; d++) {
            float4 w = cW.w1[c4 * 16 + d];
            t[0][d] = fmaf(xv0.x, w.x, fmaf(xv0.y, w.y, fmaf(xv0.z, w.z, fmaf(xv0.w, w.w, t[0][d]))));
            t[1][d] = fmaf(xv1.x, w.x, fmaf(xv1.y, w.y, fmaf(xv1.z, w.z, fmaf(xv1.w, w.w, t[1][d]))));
            t[2][d] = fmaf(xv2.x, w.x, fmaf(xv2.y, w.y, fmaf(xv2.z, w.z, fmaf(xv2.w, w.w, t[2][d]))));
            t[3][d] = fmaf(xv3.x, w.x, fmaf(xv3.y, w.y, fmaf(xv3.z, w.z, fmaf(xv3.w, w.w, t[3][d]))));
        }
    }
    #pragma unroll 2
    for (int c4 = 8; c4 < 16; c4++) {              // second channel half from global
        float4 xv0 = gp[0][c4], xv1 = gp[1][c4], xv2 = gp[2][c4], xv3 = gp[3][c4];
        #pragma unroll
        for (int d = 0; d < CR; d++) {
            float4 w = cW.w1[c4 * 16 + d];
            t[0][d] = fmaf(xv0.x, w.x, fmaf(xv0.y, w.y, fmaf(xv0.z, w.z, fmaf(xv0.w, w.w, t[0][d]))));
            t[1][d] = fmaf(xv1.x, w.x, fmaf(xv1.y, w.y, fmaf(xv1.z, w.z, fmaf(xv1.w, w.w, t[1][d]))));
            t[2][d] = fmaf(xv2.x, w.x, fmaf(xv2.y, w.y, fmaf(xv2.z, w.z, fmaf(xv2.w, w.w, t[2][d]))));
            t[3][d] = fmaf(xv3.x, w.x, fmaf(xv3.y, w.y, fmaf(xv3.z, w.z, fmaf(xv3.w, w.w, t[3][d]))));
        }
    }

    // relu px0/1 (stay in regs); relu + stash px2/3 to smem (lane-contiguous)
    #pragma unroll
    for (int d = 0; d < CR; d++) {
        t[0][d] = fmaxf(t[0][d], 0.f);
        t[1][d] = fmaxf(t[1][d], 0.f);
        tbuf[(0 * CR + d) * 128 + tid] = fmaxf(t[2][d], 0.f);
        tbuf[(1 * CR + d) * 128 + tid] = fmaxf(t[3][d], 0.f);
    }

    // ---- phase C: per-pixel 3x3 kernels; a2/a3 read back from smem ----
    float4 k[4][TAPS];
    #pragma unroll
    for (int tap = 0; tap < TAPS; tap++) {
        float4 b = cW.b2[tap];
        k[0][tap] = b; k[1][tap] = b; k[2][tap] = b; k[3][tap] = b;
    }
    #pragma unroll
    for (int d = 0; d < CR; d++) {
        float a0 = t[0][d], a1 = t[1][d];
        float a2 = tbuf[(0 * CR + d) * 128 + tid];
        float a3 = tbuf[(1 * CR + d) * 128 + tid];
        #pragma unroll
        for (int tap = 0; tap < TAPS; tap++) {
            float4 w = cW.w2[d * TAPS + tap];
            k[0][tap].x = fmaf(a0, w.x, k[0][tap].x); k[0][tap].y = fmaf(a0, w.y, k[0][tap].y);
            k[0][tap].z = fmaf(a0, w.z, k[0][tap].z); k[0][tap].w = fmaf(a0, w.w, k[0][tap].w);
            k[1][tap].x = fmaf(a1, w.x, k[1][tap].x); k[1][tap].y = fmaf(a1, w.y, k[1][tap].y);
            k[1][tap].z = fmaf(a1, w.z, k[1][tap].z); k[1][tap].w = fmaf(a1, w.w, k[1][tap].w);
            k[2][tap].x = fmaf(a2, w.x, k[2][tap].x); k[2][tap].y = fmaf(a2, w.y, k[2][tap].y);
            k[2][tap].z = fmaf(a2, w.z, k[2][tap].z); k[2][tap].w = fmaf(a2, w.w, k[2][tap].w);
            k[3][tap].x = fmaf(a3, w.x, k[3][tap].x); k[3][tap].y = fmaf(a3, w.y, k[3][tap].y);
            k[3][tap].z = fmaf(a3, w.z, k[3][tap].z); k[3][tap].w = fmaf(a3, w.w, k[3][tap].w);
        }
    }

    // ---- phase D: two channel-half passes; 6 smem rows serve 4 outputs ----
    float4* o[4];
    #pragma unroll
    for (int p = 0; p < 4; p++)
        o[p] = (float4*)(out + (((size_t)bz * HH + gy0 + 4 * qy + p) * WW + gx0 + tx) * CC);
    const int rowstep = HW * PSTR;
    const float4* base = tile4 + (4 * qy * HW + tx) * PSTR;

    #pragma unroll
    for (int uh = 0; uh < 2; uh++) {
        if (uh) {
            __syncthreads();
            load_tile_half(smem_base, xb, gy0, gx0, 8, tid);
            __syncthreads();
        }
        #pragma unroll 2
        for (int u = 0; u < 8; u++) {
            float4 a0 = make_float4(0.f, 0.f, 0.f, 0.f);
            float4 a1 = make_float4(0.f, 0.f, 0.f, 0.f);
            float4 a2 = make_float4(0.f, 0.f, 0.f, 0.f);
            float4 a3 = make_float4(0.f, 0.f, 0.f, 0.f);
            #pragma unroll
            for (int dj = 0; dj < 3; dj++) {
                const float4* col = base + dj * PSTR + u;
                float4 r0 = col[0];
                float4 r1 = col[rowstep];
                float4 r2 = col[2 * rowstep];
                float4 r3 = col[3 * rowstep];
                float4 r4 = col[4 * rowstep];
                float4 r5 = col[5 * rowstep];
                fma4(a0, k[0][dj],     r0);
                fma4(a0, k[0][3 + dj], r1);
                fma4(a0, k[0][6 + dj], r2);
                fma4(a1, k[1][dj],     r1);
                fma4(a1, k[1][3 + dj], r2);
                fma4(a1, k[1][6 + dj], r3);
                fma4(a2, k[2][dj],     r2);
                fma4(a2, k[2][3 + dj], r3);
                fma4(a2, k[2][6 + dj], r4);
                fma4(a3, k[3][dj],     r3);
                fma4(a3, k[3][3 + dj], r4);
                fma4(a3, k[3][6 + dj], r5);
            }
            o[0][uh * 8 + u] = a0;
            o[1][uh * 8 + u] = a1;
            o[2][uh * 8 + u] = a2;
            o[3][uh * 8 + u] = a3;
        }
    }
}

extern "C" void kernel_launch(void* const* d_in, const int* in_sizes, int n_in,
                              void* d_out, int out_size) {
    const float* x     = (const float*)d_in[0];
    const float* w1    = (const float*)d_in[1];
    const float* b1    = (const float*)d_in[2];
    const float* gamma = (const float*)d_in[3];
    const float* beta  = (const float*)d_in[4];
    const float* mean  = (const float*)d_in[5];
    const float* var   = (const float*)d_in[6];
    const float* w2    = (const float*)d_in[7];
    const float* b2    = (const float*)d_in[8];
    float* out = (float*)d_out;

    int B = in_sizes[0] / (HH * WW * CC);

    // 1) fold BN + stage weights
    involution_prep_kernel<<<1, 256>>>(w1, b1, gamma, beta, mean, var, w2, b2);

    // 2) copy into __constant__ (D2D memcpy node, graph-capturable)
    static void* scratch_addr = nullptr;
    if (!scratch_addr) cudaGetSymbolAddress(&scratch_addr, scratchW);
    cudaMemcpyToSymbolAsync(cW, scratch_addr, sizeof(ConstW), 0,
                            cudaMemcpyDeviceToDevice, 0);

    // 3) main fused kernel
    static bool attr_set = false;
    if (!attr_set) {
        cudaFuncSetAttribute(involution_fused_kernel,
                             cudaFuncAttributeMaxDynamicSharedMemorySize, SMEM_BYTES);
        attr_set = true;
    }
    dim3 grid(WW / TW, HH / TH, B);   // 12 x 6 x 8
    involution_fused_kernel<<<grid, 128, SMEM_BYTES>>>(x, out);
}

// round 14
// speedup vs baseline: 1.1054x; 1.1054x over previous
#include <cuda_runtime.h>
#include <cstddef>

// Involution (B=8, H=W=192, C=64, G=4, K=3, R=4 -> cr=16)
// R14: R12 base (32x16 tile, 128 thr, 4 vertical px/thread, channel-split
// smem tile, cp.async) with:
//  - phase C computed in two sequential pixel-pairs (reg peak ~210, no spill)
//  - w2/b2 staged in smem (broadcast LDS, off the constant port)
//  - w1/b1 remain in __constant__

#define HH 192
#define WW 192
#define CC 64
#define CR 16
#define TAPS 9

constexpr int TW = 16;                                // tile width
constexpr int TH = 32;                                // tile height
constexpr int HW = 18;                                // halo width
constexpr int HT = 34;                                // halo height
constexpr int PSTR = 9;                               // f4 per pixel (8 data + 1 pad)
constexpr int TILE_F4 = HT * HW * PSTR;               // 5508
constexpr int W2_F4 = 144;
constexpr int B2_F4 = 9;
constexpr int SMEM_BYTES = (TILE_F4 + W2_F4 + B2_F4) * 16;  // 90576 B

struct ConstW {
    float4 w1[256];   // [c4=16][d=16], BN folded
    float  b1[16];    // BN-folded bias
};
__constant__ ConstW cW;

struct Scratch {
    ConstW c;
    float4 w2[144];   // [d=16][tap=9], f4 over 4 groups
    float4 b2[9];
};
__device__ Scratch scratchW;

__global__ void involution_prep_kernel(const float* __restrict__ w1,
                                       const float* __restrict__ b1,
                                       const float* __restrict__ gamma,
                                       const float* __restrict__ beta,
                                       const float* __restrict__ mean,
                                       const float* __restrict__ var,
                                       const float* __restrict__ w2,
                                       const float* __restrict__ b2) {
    __shared__ float s[16];
    int tid = threadIdx.x;   // 256 threads
    if (tid < 16) {
        float sc = gamma[tid] * rsqrtf(var[tid] + 1e-3f);
        s[tid] = sc;
        scratchW.c.b1[tid] = (b1[tid] - mean[tid]) * sc + beta[tid];
    }
    __syncthreads();
    {
        int d  = tid & 15;
        int c4 = tid >> 4;
        float sc = s[d];
        scratchW.c.w1[tid] = make_float4(w1[(4 * c4 + 0) * CR + d] * sc,
                                         w1[(4 * c4 + 1) * CR + d] * sc,
                                         w1[(4 * c4 + 2) * CR + d] * sc,
                                         w1[(4 * c4 + 3) * CR + d] * sc);
    }
    if (tid < 144) scratchW.w2[tid] = ((const float4*)w2)[tid];
    if (tid < 9)   scratchW.b2[tid] = ((const float4*)b2)[tid];
}

__device__ __forceinline__ void fma4(float4& a, const float4& k, const float4& v) {
    a.x = fmaf(k.x, v.x, a.x);
    a.y = fmaf(k.y, v.y, a.y);
    a.z = fmaf(k.z, v.z, a.z);
    a.w = fmaf(k.w, v.w, a.w);
}

__device__ __forceinline__ void cp16(unsigned dst, const void* src, int sz) {
    asm volatile("cp.async.cg.shared.global [%0], [%1], 16, %2;"
                 :: "r"(dst), "l"(src), "r"(sz) : "memory");
}

// load one channel-half (f4 base = uoff) of the 34x18 halo tile, zero-fill OOB
__device__ __forceinline__ void load_tile_half(unsigned smem_base,
                                               const float* __restrict__ xb,
                                               int gy0, int gx0, int uoff, int tid) {
    for (int s = tid; s < HT * HW * 8; s += 128) {
        int u   = s & 7;
        int pix = s >> 3;
        int py  = pix / HW;
        int px  = pix - py * HW;
        int gh  = gy0 - 1 + py;
        int gw  = gx0 - 1 + px;
        bool ok = ((unsigned)gh < HH) && ((unsigned)gw < WW);
        const float4* src = (const float4*)(xb + ((size_t)(ok ? gh : 0) * WW + (ok ? gw : 0)) * CC)
                            + uoff + u;
        cp16(smem_base + (unsigned)(pix * PSTR + u) * 16u, src, ok ? 16 : 0);
    }
    asm volatile("cp.async.commit_group;\n\tcp.async.wait_group 0;" ::: "memory");
}

__global__ __launch_bounds__(128, 2)
void involution_fused_kernel(const float* __restrict__ x,
                             float* __restrict__ out) {
    extern __shared__ float4 sm4[];
    float4* tile4 = sm4;                      // [34*18 px][9 f4]
    float4* w2s   = sm4 + TILE_F4;            // [144]
    float4* b2s   = w2s + W2_F4;              // [9]

    const int tid = threadIdx.x;              // 0..127
    const int tx  = tid & 15;
    const int qy  = tid >> 4;                 // 0..7 -> output rows 4qy..4qy+3
    const int gx0 = blockIdx.x * TW;
    const int gy0 = blockIdx.y * TH;
    const int bz  = blockIdx.z;

    const float* xb = x + (size_t)bz * ((size_t)HH * WW * CC);
    unsigned smem_base = (unsigned)__cvta_generic_to_shared(tile4);

    // ---- stage w2/b2 into smem (coalesced from L2-resident scratch) ----
    #pragma unroll
    for (int i = tid; i < W2_F4; i += 128) w2s[i] = scratchW.w2[i];
    if (tid < B2_F4) b2s[tid] = scratchW.b2[tid];

    // ---- tile half u0-7 ----
    load_tile_half(smem_base, xb, gy0, gx0, 0, tid);
    __syncthreads();

    // ---- phase B: t[p][d] = relu(x_p . w1' + b1'), 4 vertical pixels ----
    const float4* xc[4];
    const float4* gp[4];
    #pragma unroll
    for (int p = 0; p < 4; p++) {
        xc[p] = tile4 + ((4 * qy + p + 1) * HW + (tx + 1)) * PSTR;
        gp[p] = (const float4*)(xb + ((size_t)(gy0 + 4 * qy + p) * WW + gx0 + tx) * CC);
    }

    float t[4][CR];
    #pragma unroll
    for (int d = 0; d < CR; d++) {
        float b = cW.b1[d];
        t[0][d] = b; t[1][d] = b; t[2][d] = b; t[3][d] = b;
    }

    #pragma unroll 2
    for (int c4 = 0; c4 < 8; c4++) {               // first channel half from smem
        float4 xv0 = xc[0][c4], xv1 = xc[1][c4], xv2 = xc[2][c4], xv3 = xc[3][c4];
        #pragma unroll
        for (int d = 0; d < CR; d++) {
            float4 w = cW.w1[c4 * 16 + d];
            t[0][d] = fmaf(xv0.x, w.x, fmaf(xv0.y, w.y, fmaf(xv0.z, w.z, fmaf(xv0.w, w.w, t[0][d]))));
            t[1][d] = fmaf(xv1.x, w.x, fmaf(xv1.y, w.y, fmaf(xv1.z, w.z, fmaf(xv1.w, w.w, t[1][d]))));
            t[2][d] = fmaf(xv2.x, w.x, fmaf(xv2.y, w.y, fmaf(xv2.z, w.z, fmaf(xv2.w, w.w, t[2][d]))));
            t[3][d] = fmaf(xv3.x, w.x, fmaf(xv3.y, w.y, fmaf(xv3.z, w.z, fmaf(xv3.w, w.w, t[3][d]))));
        }
    }
    #pragma unroll 2
    for (int c4 = 8; c4 < 16; c4++) {              // second channel half from global
        float4 xv0 = gp[0][c4], xv1 = gp[1][c4], xv2 = gp[2][c4], xv3 = gp[3][c4];
        #pragma unroll
        for (int d = 0; d < CR; d++) {
            float4 w = cW.w1[c4 * 16 + d];
            t[0][d] = fmaf(xv0.x, w.x, fmaf(xv0.y, w.y, fmaf(xv0.z, w.z, fmaf(xv0.w, w.w, t[0][d]))));
            t[1][d] = fmaf(xv1.x, w.x, fmaf(xv1.y, w.y, fmaf(xv1.z, w.z, fmaf(xv1.w, w.w, t[1][d]))));
            t[2][d] = fmaf(xv2.x, w.x, fmaf(xv2.y, w.y, fmaf(xv2.z, w.z, fmaf(xv2.w, w.w, t[2][d]))));
            t[3][d] = fmaf(xv3.x, w.x, fmaf(xv3.y, w.y, fmaf(xv3.z, w.z, fmaf(xv3.w, w.w, t[3][d]))));
        }
    }
    #pragma unroll
    for (int d = 0; d < CR; d++) {
        t[0][d] = fmaxf(t[0][d], 0.f);
        t[1][d] = fmaxf(t[1][d], 0.f);
        t[2][d] = fmaxf(t[2][d], 0.f);
        t[3][d] = fmaxf(t[3][d], 0.f);
    }

    // ---- phase C: two sequential pixel-pairs (caps live set; w2 from smem) ----
    float4 k[4][TAPS];
    #pragma unroll
    for (int pp = 0; pp < 2; pp++) {
        const int p0 = 2 * pp, p1 = 2 * pp + 1;
        #pragma unroll
        for (int tap = 0; tap < TAPS; tap++) {
            float4 b = b2s[tap];
            k[p0][tap] = b;
            k[p1][tap] = b;
        }
        #pragma unroll
        for (int d = 0; d < CR; d++) {
            float a0 = t[p0][d], a1 = t[p1][d];
            #pragma unroll
            for (int tap = 0; tap < TAPS; tap++) {
                float4 w = w2s[d * TAPS + tap];
                k[p0][tap].x = fmaf(a0, w.x, k[p0][tap].x);
                k[p0][tap].y = fmaf(a0, w.y, k[p0][tap].y);
                k[p0][tap].z = fmaf(a0, w.z, k[p0][tap].z);
                k[p0][tap].w = fmaf(a0, w.w, k[p0][tap].w);
                k[p1][tap].x = fmaf(a1, w.x, k[p1][tap].x);
                k[p1][tap].y = fmaf(a1, w.y, k[p1][tap].y);
                k[p1][tap].z = fmaf(a1, w.z, k[p1][tap].z);
                k[p1][tap].w = fmaf(a1, w.w, k[p1][tap].w);
            }
        }
    }

    // ---- phase D: two channel-half passes; 6 smem rows serve 4 outputs ----
    float4* o[4];
    #pragma unroll
    for (int p = 0; p < 4; p++)
        o[p] = (float4*)(out + (((size_t)bz * HH + gy0 + 4 * qy + p) * WW + gx0 + tx) * CC);
    const int rowstep = HW * PSTR;
    const float4* base = tile4 + (4 * qy * HW + tx) * PSTR;

    #pragma unroll
    for (int uh = 0; uh < 2; uh++) {
        if (uh) {
            __syncthreads();
            load_tile_half(smem_base, xb, gy0, gx0, 8, tid);
            __syncthreads();
        }
        #pragma unroll 2
        for (int u = 0; u < 8; u++) {
            float4 a0 = make_float4(0.f, 0.f, 0.f, 0.f);
            float4 a1 = make_float4(0.f, 0.f, 0.f, 0.f);
            float4 a2 = make_float4(0.f, 0.f, 0.f, 0.f);
            float4 a3 = make_float4(0.f, 0.f, 0.f, 0.f);
            #pragma unroll
            for (int dj = 0; dj < 3; dj++) {
                const float4* col = base + dj * PSTR + u;
                float4 r0 = col[0];
                float4 r1 = col[rowstep];
                float4 r2 = col[2 * rowstep];
                float4 r3 = col[3 * rowstep];
                float4 r4 = col[4 * rowstep];
                float4 r5 = col[5 * rowstep];
                fma4(a0, k[0][dj],     r0);
                fma4(a0, k[0][3 + dj], r1);
                fma4(a0, k[0][6 + dj], r2);
                fma4(a1, k[1][dj],     r1);
                fma4(a1, k[1][3 + dj], r2);
                fma4(a1, k[1][6 + dj], r3);
                fma4(a2, k[2][dj],     r2);
                fma4(a2, k[2][3 + dj], r3);
                fma4(a2, k[2][6 + dj], r4);
                fma4(a3, k[3][dj],     r3);
                fma4(a3, k[3][3 + dj], r4);
                fma4(a3, k[3][6 + dj], r5);
            }
            o[0][uh * 8 + u] = a0;
            o[1][uh * 8 + u] = a1;
            o[2][uh * 8 + u] = a2;
            o[3][uh * 8 + u] = a3;
        }
    }
}

extern "C" void kernel_launch(void* const* d_in, const int* in_sizes, int n_in,
                              void* d_out, int out_size) {
    const float* x     = (const float*)d_in[0];
    const float* w1    = (const float*)d_in[1];
    const float* b1    = (const float*)d_in[2];
    const float* gamma = (const float*)d_in[3];
    const float* beta  = (const float*)d_in[4];
    const float* mean  = (const float*)d_in[5];
    const float* var   = (const float*)d_in[6];
    const float* w2    = (const float*)d_in[7];
    const float* b2    = (const float*)d_in[8];
    float* out = (float*)d_out;

    int B = in_sizes[0] / (HH * WW * CC);

    // 1) fold BN + stage weights
    involution_prep_kernel<<<1, 256>>>(w1, b1, gamma, beta, mean, var, w2, b2);

    // 2) copy w1/b1 into __constant__ (D2D memcpy node, graph-capturable)
    static char* scratch_addr = nullptr;
    if (!scratch_addr) cudaGetSymbolAddress((void**)&scratch_addr, scratchW);
    cudaMemcpyToSymbolAsync(cW, scratch_addr + offsetof(Scratch, c),
                            sizeof(ConstW), 0, cudaMemcpyDeviceToDevice, 0);

    // 3) main fused kernel
    static bool attr_set = false;
    if (!attr_set) {
        cudaFuncSetAttribute(involution_fused_kernel,
                             cudaFuncAttributeMaxDynamicSharedMemorySize, SMEM_BYTES);
        attr_set = true;
    }
    dim3 grid(WW / TW, HH / TH, B);   // 12 x 6 x 8
    involution_fused_kernel<<<grid, 128, SMEM_BYTES>>>(x, out);
}

// round 15
// speedup vs baseline: 1.2553x; 1.1356x over previous
#include <cuda_runtime.h>
#include <cstddef>

// Involution (B=8, H=W=192, C=64, G=4, K=3, R=4 -> cr=16)
// R15: R14 structure (32x16 tile, 128 thr, 4 vertical px/thread, channel-split
// smem tile, cp.async, w2/b2 smem, w1/b1 const, pair-split phase C) with all
// FMA math packed into fma.rn.f32x2 under the 255-reg budget.

#define HH 192
#define WW 192
#define CC 64
#define CR 16
#define TAPS 9

typedef unsigned long long u64;

constexpr int TW = 16;
constexpr int TH = 32;
constexpr int HW = 18;
constexpr int HT = 34;
constexpr int PSTR = 9;                               // f4 per pixel (8 data + 1 pad)
constexpr int TILE_F4 = HT * HW * PSTR;               // 5508
constexpr int W2_F4 = 144;
constexpr int B2_F4 = 9;
constexpr int SMEM_BYTES = (TILE_F4 + W2_F4 + B2_F4) * 16;  // 90576 B

struct ConstW {
    u64 w1p[16][8][4];   // [c4][dpair][cc]: {w1f[4c4+cc][2dp], w1f[4c4+cc][2dp+1]}, BN folded
    u64 b1p[8];          // packed BN-folded bias pairs
};
__constant__ ConstW cW;

struct Scratch {
    ConstW c;
    float4 w2[144];      // [d=16][tap=9], f4 over 4 groups
    float4 b2[9];
};
__device__ Scratch scratchW;

__device__ __forceinline__ u64 pack2(float a, float b) {
    u64 r; asm("mov.b64 %0, {%1, %2};" : "=l"(r) : "f"(a), "f"(b)); return r;
}
__device__ __forceinline__ u64 dup2(float v) {
    u64 r; asm("mov.b64 %0, {%1, %1};" : "=l"(r) : "f"(v)); return r;
}
__device__ __forceinline__ float2 unpk(u64 p) {
    float2 f; asm("mov.b64 {%0, %1}, %2;" : "=f"(f.x), "=f"(f.y) : "l"(p)); return f;
}
__device__ __forceinline__ u64 fma2(u64 a, u64 b, u64 c) {
    u64 r; asm("fma.rn.f32x2 %0, %1, %2, %3;" : "=l"(r) : "l"(a), "l"(b), "l"(c)); return r;
}

__global__ void involution_prep_kernel(const float* __restrict__ w1,
                                       const float* __restrict__ b1,
                                       const float* __restrict__ gamma,
                                       const float* __restrict__ beta,
                                       const float* __restrict__ mean,
                                       const float* __restrict__ var,
                                       const float* __restrict__ w2,
                                       const float* __restrict__ b2) {
    __shared__ float s[16];
    int tid = threadIdx.x;   // 256 threads
    if (tid < 16) {
        float sc = gamma[tid] * rsqrtf(var[tid] + 1e-3f);
        s[tid] = sc;
    }
    __syncthreads();
    if (tid < 8) {
        float a = (b1[2 * tid]     - mean[2 * tid])     * s[2 * tid]     + beta[2 * tid];
        float b = (b1[2 * tid + 1] - mean[2 * tid + 1]) * s[2 * tid + 1] + beta[2 * tid + 1];
        scratchW.c.b1p[tid] = pack2(a, b);
    }
    for (int i = tid; i < 512; i += 256) {
        int c4 = i >> 5;
        int dp = (i >> 2) & 7;
        int cc = i & 3;
        int c  = 4 * c4 + cc;
        scratchW.c.w1p[c4][dp][cc] = pack2(w1[c * CR + 2 * dp]     * s[2 * dp],
                                           w1[c * CR + 2 * dp + 1] * s[2 * dp + 1]);
    }
    if (tid < 144) scratchW.w2[tid] = ((const float4*)w2)[tid];
    if (tid < 9)   scratchW.b2[tid] = ((const float4*)b2)[tid];
}

__device__ __forceinline__ void cp16(unsigned dst, const void* src, int sz) {
    asm volatile("cp.async.cg.shared.global [%0], [%1], 16, %2;"
                 :: "r"(dst), "l"(src), "r"(sz) : "memory");
}

// load one channel-half (f4 base = uoff) of the 34x18 halo tile, zero-fill OOB
__device__ __forceinline__ void load_tile_half(unsigned smem_base,
                                               const float* __restrict__ xb,
                                               int gy0, int gx0, int uoff, int tid) {
    for (int s = tid; s < HT * HW * 8; s += 128) {
        int u   = s & 7;
        int pix = s >> 3;
        int py  = pix / HW;
        int px  = pix - py * HW;
        int gh  = gy0 - 1 + py;
        int gw  = gx0 - 1 + px;
        bool ok = ((unsigned)gh < HH) && ((unsigned)gw < WW);
        const float4* src = (const float4*)(xb + ((size_t)(ok ? gh : 0) * WW + (ok ? gw : 0)) * CC)
                            + uoff + u;
        cp16(smem_base + (unsigned)(pix * PSTR + u) * 16u, src, ok ? 16 : 0);
    }
    asm volatile("cp.async.commit_group;\n\tcp.async.wait_group 0;" ::: "memory");
}

__global__ __launch_bounds__(128, 2)
void involution_fused_kernel(const float* __restrict__ x,
                             float* __restrict__ out) {
    extern __shared__ float4 sm4[];
    float4* tile4 = sm4;                      // [34*18 px][9 f4]
    float4* w2s   = sm4 + TILE_F4;            // [144]
    float4* b2s   = w2s + W2_F4;              // [9]

    const int tid = threadIdx.x;              // 0..127
    const int tx  = tid & 15;
    const int qy  = tid >> 4;                 // 0..7 -> output rows 4qy..4qy+3
    const int gx0 = blockIdx.x * TW;
    const int gy0 = blockIdx.y * TH;
    const int bz  = blockIdx.z;

    const float* xb = x + (size_t)bz * ((size_t)HH * WW * CC);
    unsigned smem_base = (unsigned)__cvta_generic_to_shared(tile4);

    // ---- stage w2/b2 into smem ----
    #pragma unroll
    for (int i = tid; i < W2_F4; i += 128) w2s[i] = scratchW.w2[i];
    if (tid < B2_F4) b2s[tid] = scratchW.b2[tid];

    // ---- tile half u0-7 ----
    load_tile_half(smem_base, xb, gy0, gx0, 0, tid);
    __syncthreads();

    // ---- phase B: t2[p][dp] = x_p . w1' + b1' (packed d-pairs), 4 pixels ----
    const float4* xc[4];
    const float4* gp[4];
    #pragma unroll
    for (int p = 0; p < 4; p++) {
        xc[p] = tile4 + ((4 * qy + p + 1) * HW + (tx + 1)) * PSTR;
        gp[p] = (const float4*)(xb + ((size_t)(gy0 + 4 * qy + p) * WW + gx0 + tx) * CC);
    }

    u64 t2[4][8];
    #pragma unroll
    for (int dp = 0; dp < 8; dp++) {
        u64 b = cW.b1p[dp];
        t2[0][dp] = b; t2[1][dp] = b; t2[2][dp] = b; t2[3][dp] = b;
    }

    #pragma unroll 2
    for (int c4 = 0; c4 < 8; c4++) {               // first channel half from smem
        u64 xd[4][4];
        #pragma unroll
        for (int p = 0; p < 4; p++) {
            float4 xv = xc[p][c4];
            xd[p][0] = dup2(xv.x); xd[p][1] = dup2(xv.y);
            xd[p][2] = dup2(xv.z); xd[p][3] = dup2(xv.w);
        }
        #pragma unroll
        for (int dp = 0; dp < 8; dp++) {
            const u64* w = cW.w1p[c4][dp];
            #pragma unroll
            for (int p = 0; p < 4; p++) {
                u64 acc = t2[p][dp];
                acc = fma2(xd[p][0], w[0], acc);
                acc = fma2(xd[p][1], w[1], acc);
                acc = fma2(xd[p][2], w[2], acc);
                acc = fma2(xd[p][3], w[3], acc);
                t2[p][dp] = acc;
            }
        }
    }
    #pragma unroll 2
    for (int c4 = 8; c4 < 16; c4++) {              // second channel half from global
        u64 xd[4][4];
        #pragma unroll
        for (int p = 0; p < 4; p++) {
            float4 xv = gp[p][c4];
            xd[p][0] = dup2(xv.x); xd[p][1] = dup2(xv.y);
            xd[p][2] = dup2(xv.z); xd[p][3] = dup2(xv.w);
        }
        #pragma unroll
        for (int dp = 0; dp < 8; dp++) {
            const u64* w = cW.w1p[c4][dp];
            #pragma unroll
            for (int p = 0; p < 4; p++) {
                u64 acc = t2[p][dp];
                acc = fma2(xd[p][0], w[0], acc);
                acc = fma2(xd[p][1], w[1], acc);
                acc = fma2(xd[p][2], w[2], acc);
                acc = fma2(xd[p][3], w[3], acc);
                t2[p][dp] = acc;
            }
        }
    }

    // unpack + relu -> scalar t[4][16]
    float t[4][CR];
    #pragma unroll
    for (int p = 0; p < 4; p++) {
        #pragma unroll
        for (int dp = 0; dp < 8; dp++) {
            float2 f = unpk(t2[p][dp]);
            t[p][2 * dp]     = fmaxf(f.x, 0.f);
            t[p][2 * dp + 1] = fmaxf(f.y, 0.f);
        }
    }

    // ---- phase C: two sequential pixel-pairs, packed group-pairs ----
    u64 k2[4][TAPS][2];
    const ulonglong2* w2p = (const ulonglong2*)w2s;
    const ulonglong2* b2p = (const ulonglong2*)b2s;
    #pragma unroll
    for (int pp = 0; pp < 2; pp++) {
        const int p0 = 2 * pp, p1 = 2 * pp + 1;
        #pragma unroll
        for (int tap = 0; tap < TAPS; tap++) {
            ulonglong2 b = b2p[tap];
            k2[p0][tap][0] = b.x; k2[p0][tap][1] = b.y;
            k2[p1][tap][0] = b.x; k2[p1][tap][1] = b.y;
        }
        #pragma unroll
        for (int d = 0; d < CR; d++) {
            u64 a0 = dup2(t[p0][d]);
            u64 a1 = dup2(t[p1][d]);
            #pragma unroll
            for (int tap = 0; tap < TAPS; tap++) {
                ulonglong2 w = w2p[d * TAPS + tap];
                k2[p0][tap][0] = fma2(a0, w.x, k2[p0][tap][0]);
                k2[p0][tap][1] = fma2(a0, w.y, k2[p0][tap][1]);
                k2[p1][tap][0] = fma2(a1, w.x, k2[p1][tap][0]);
                k2[p1][tap][1] = fma2(a1, w.y, k2[p1][tap][1]);
            }
        }
    }

    // ---- phase D: two channel-half passes; 6 smem rows serve 4 outputs ----
    ulonglong2* o[4];
    #pragma unroll
    for (int p = 0; p < 4; p++)
        o[p] = (ulonglong2*)(out + (((size_t)bz * HH + gy0 + 4 * qy + p) * WW + gx0 + tx) * CC);
    const int rowstep = HW * PSTR;
    const float4* base = tile4 + (4 * qy * HW + tx) * PSTR;

    #pragma unroll
    for (int uh = 0; uh < 2; uh++) {
        if (uh) {
            __syncthreads();
            load_tile_half(smem_base, xb, gy0, gx0, 8, tid);
            __syncthreads();
        }
        #pragma unroll 2
        for (int u = 0; u < 8; u++) {
            u64 a[4][2];
            #pragma unroll
            for (int p = 0; p < 4; p++) { a[p][0] = 0; a[p][1] = 0; }   // {0.f,0.f}
            #pragma unroll
            for (int dj = 0; dj < 3; dj++) {
                const float4* col = base + dj * PSTR + u;
                ulonglong2 r0 = *(const ulonglong2*)(col);
                ulonglong2 r1 = *(const ulonglong2*)(col + rowstep);
                ulonglong2 r2 = *(const ulonglong2*)(col + 2 * rowstep);
                ulonglong2 r3 = *(const ulonglong2*)(col + 3 * rowstep);
                ulonglong2 r4 = *(const ulonglong2*)(col + 4 * rowstep);
                ulonglong2 r5 = *(const ulonglong2*)(col + 5 * rowstep);
                a[0][0] = fma2(k2[0][dj][0],     r0.x, a[0][0]);
                a[0][1] = fma2(k2[0][dj][1],     r0.y, a[0][1]);
                a[0][0] = fma2(k2[0][3 + dj][0], r1.x, a[0][0]);
                a[0][1] = fma2(k2[0][3 + dj][1], r1.y, a[0][1]);
                a[0][0] = fma2(k2[0][6 + dj][0], r2.x, a[0][0]);
                a[0][1] = fma2(k2[0][6 + dj][1], r2.y, a[0][1]);
                a[1][0] = fma2(k2[1][dj][0],     r1.x, a[1][0]);
                a[1][1] = fma2(k2[1][dj][1],     r1.y, a[1][1]);
                a[1][0] = fma2(k2[1][3 + dj][0], r2.x, a[1][0]);
                a[1][1] = fma2(k2[1][3 + dj][1], r2.y, a[1][1]);
                a[1][0] = fma2(k2[1][6 + dj][0], r3.x, a[1][0]);
                a[1][1] = fma2(k2[1][6 + dj][1], r3.y, a[1][1]);
                a[2][0] = fma2(k2[2][dj][0],     r2.x, a[2][0]);
                a[2][1] = fma2(k2[2][dj][1],     r2.y, a[2][1]);
                a[2][0] = fma2(k2[2][3 + dj][0], r3.x, a[2][0]);
                a[2][1] = fma2(k2[2][3 + dj][1], r3.y, a[2][1]);
                a[2][0] = fma2(k2[2][6 + dj][0], r4.x, a[2][0]);
                a[2][1] = fma2(k2[2][6 + dj][1], r4.y, a[2][1]);
                a[3][0] = fma2(k2[3][dj][0],     r3.x, a[3][0]);
                a[3][1] = fma2(k2[3][dj][1],     r3.y, a[3][1]);
                a[3][0] = fma2(k2[3][3 + dj][0], r4.x, a[3][0]);
                a[3][1] = fma2(k2[3][3 + dj][1], r4.y, a[3][1]);
                a[3][0] = fma2(k2[3][6 + dj][0], r5.x, a[3][0]);
                a[3][1] = fma2(k2[3][6 + dj][1], r5.y, a[3][1]);
            }
            #pragma unroll
            for (int p = 0; p < 4; p++) {
                ulonglong2 v;
                v.x = a[p][0]; v.y = a[p][1];
                o[p][uh * 8 + u] = v;
            }
        }
    }
}

extern "C" void kernel_launch(void* const* d_in, const int* in_sizes, int n_in,
                              void* d_out, int out_size) {
    const float* x     = (const float*)d_in[0];
    const float* w1    = (const float*)d_in[1];
    const float* b1    = (const float*)d_in[2];
    const float* gamma = (const float*)d_in[3];
    const float* beta  = (const float*)d_in[4];
    const float* mean  = (const float*)d_in[5];
    const float* var   = (const float*)d_in[6];
    const float* w2    = (const float*)d_in[7];
    const float* b2    = (const float*)d_in[8];
    float* out = (float*)d_out;

    int B = in_sizes[0] / (HH * WW * CC);

    // 1) fold BN + pack weights
    involution_prep_kernel<<<1, 256>>>(w1, b1, gamma, beta, mean, var, w2, b2);

    // 2) copy packed w1/b1 into __constant__ (D2D memcpy node, capturable)
    static char* scratch_addr = nullptr;
    if (!scratch_addr) cudaGetSymbolAddress((void**)&scratch_addr, scratchW);
    cudaMemcpyToSymbolAsync(cW, scratch_addr + offsetof(Scratch, c),
                            sizeof(ConstW), 0, cudaMemcpyDeviceToDevice, 0);

    // 3) main fused kernel
    static bool attr_set = false;
    if (!attr_set) {
        cudaFuncSetAttribute(involution_fused_kernel,
                             cudaFuncAttributeMaxDynamicSharedMemorySize, SMEM_BYTES);
        attr_set = true;
    }
    dim3 grid(WW / TW, HH / TH, B);   // 12 x 6 x 8
    involution_fused_kernel<<<grid, 128, SMEM_BYTES>>>(x, out);
}